// round 1
// baseline (speedup 1.0000x reference)
#include <cuda_runtime.h>
#include <math.h>

// Problem constants
#define BATCH 512
#define HID   512
#define WDIM  1024
#define VOCAB 4004
#define TSTEPS 27
#define SLEN  80
#define NGATE 2048          // 4*HID
#define LSTM_IN 1536        // WDIM + HID

typedef unsigned long long ull;

// ---------------- scratch (device globals; allocation-free) ----------------
__device__ float g_a2[HID];
__device__ float g_a1[HID];
__device__ float g_a0e[HID];
__device__ float g_ctx[BATCH * HID];
__device__ float g_h[BATCH * HID];
__device__ float g_c[BATCH * HID];
__device__ float g_Gbase[BATCH * NGATE];      // ctx @ W_ih_ctx^T + b_ih + b_hh
__device__ float g_gates[BATCH * NGATE];
__device__ float g_Eproj[VOCAB * NGATE];      // embedding @ W_ih_word^T  (32.8 MB)
__device__ ull   g_tokpack[BATCH];

// ---------------- small helpers ----------------
__device__ __forceinline__ ull ffma2(ull a, ull b, ull c) {
    ull d;
    asm("fma.rn.f32x2 %0, %1, %2, %3;" : "=l"(d) : "l"(a), "l"(b), "l"(c));
    return d;
}
__device__ __forceinline__ ull bcast2(float x) {
    ull r;
    asm("mov.b64 %0, {%1, %2};" : "=l"(r) : "f"(x), "f"(x));
    return r;
}
__device__ __forceinline__ float2 unpack2(ull v) {
    float2 r;
    asm("mov.b64 {%0, %1}, %2;" : "=f"(r.x), "=f"(r.y) : "l"(v));
    return r;
}
__device__ __forceinline__ unsigned f2ord(float x) {
    unsigned u = __float_as_uint(x);
    return (u & 0x80000000u) ? ~u : (u | 0x80000000u);
}
__device__ __forceinline__ int decode_tok(ull p) {
    return (int)(0xFFFFFFFFu - (unsigned)(p & 0xFFFFFFFFull));
}
__device__ __forceinline__ float sigmoidf_(float x) {
    return 1.0f / (1.0f + expf(-x));
}

// ---------------- init h, c ----------------
__global__ void init_hc_kernel(const float* __restrict__ h0) {
    int b = blockIdx.x, u = threadIdx.x;
    g_h[b * HID + u] = h0[b * HID + u];   // encoder_last_hidden_state[0]
    g_c[b * HID + u] = 0.0f;
}

// ---------------- a-chain mat-vecs: out[j] = sum_h M[h,j] * vin[h] ----------
__global__ void matvecT_kernel(const float* __restrict__ Mt, int ld,
                               const float* __restrict__ vin_ext, int stage) {
    __shared__ float red[256];
    int j = blockIdx.x;
    const float* vin = (stage == 0) ? vin_ext : (stage == 1 ? g_a2 : g_a1);
    float acc = 0.0f;
    for (int h = threadIdx.x; h < HID; h += 256)
        acc += Mt[(size_t)h * ld + j] * vin[h];
    red[threadIdx.x] = acc;
    __syncthreads();
    for (int s = 128; s > 0; s >>= 1) {
        if (threadIdx.x < s) red[threadIdx.x] += red[threadIdx.x + s];
        __syncthreads();
    }
    if (threadIdx.x == 0) {
        float r = red[0];
        if (stage == 0)      g_a2[j]  = r;
        else if (stage == 1) g_a1[j]  = r;
        else                 g_a0e[j] = r;
    }
}

// ---------------- attention scores + softmax + context (step-invariant) ----
__global__ void attn_ctx_kernel(const float* __restrict__ enc) {
    __shared__ float sa[HID];
    __shared__ float sE[SLEN];
    __shared__ float sW[SLEN];
    int b = blockIdx.x;
    int tid = threadIdx.x;

    sa[tid]       = g_a0e[tid];
    sa[tid + 256] = g_a0e[tid + 256];
    __syncthreads();

    int w = tid >> 5, lane = tid & 31;
    for (int s = w; s < SLEN; s += 8) {
        const float* row = enc + ((size_t)b * SLEN + s) * HID;
        float acc = 0.0f;
        for (int k = lane; k < HID; k += 32) acc += row[k] * sa[k];
        #pragma unroll
        for (int off = 16; off > 0; off >>= 1)
            acc += __shfl_xor_sync(0xffffffffu, acc, off);
        if (lane == 0) sE[s] = acc;
    }
    __syncthreads();

    if (tid < 32) {
        float v0 = (tid      < SLEN) ? sE[tid]      : -INFINITY;
        float v1 = (tid + 32 < SLEN) ? sE[tid + 32] : -INFINITY;
        float v2 = (tid + 64 < SLEN) ? sE[tid + 64] : -INFINITY;
        float m = fmaxf(v0, fmaxf(v1, v2));
        #pragma unroll
        for (int off = 16; off > 0; off >>= 1)
            m = fmaxf(m, __shfl_xor_sync(0xffffffffu, m, off));
        float e0 = (tid      < SLEN) ? expf(v0 - m) : 0.0f;
        float e1 = (tid + 32 < SLEN) ? expf(v1 - m) : 0.0f;
        float e2 = (tid + 64 < SLEN) ? expf(v2 - m) : 0.0f;
        float s = e0 + e1 + e2;
        #pragma unroll
        for (int off = 16; off > 0; off >>= 1)
            s += __shfl_xor_sync(0xffffffffu, s, off);
        if (tid      < SLEN) sW[tid]      = e0 / s;
        if (tid + 32 < SLEN) sW[tid + 32] = e1 / s;
        if (tid + 64 < SLEN) sW[tid + 64] = e2 / s;
    }
    __syncthreads();

    for (int h = tid; h < HID; h += 256) {
        float acc = 0.0f;
        for (int s = 0; s < SLEN; s++)
            acc += sW[s] * enc[((size_t)b * SLEN + s) * HID + h];
        g_ctx[b * HID + h] = acc;
    }
}

// ---------------- fp32x2 GEMM: C[m,n] = sum_k A[m,k]*B[n,k] (+epilogue) -----
// MODE 0: A=g_ctx   -> C=g_Gbase (+bias1+bias2)
// MODE 1: A=g_h     -> g_gates  += G_base[m] + E_proj[tok[m]]
// MODE 2: A=g_h     -> d_out logits (+bias1) + fused argmax atomics
// MODE 3: A=param   -> C=g_Eproj
// Tile: BM=64, BN=128, BK=32, 256 threads, thread-tile 4x8.
template <int MODE>
__global__ __launch_bounds__(256, 2)
void gemm_kernel(const float* __restrict__ Ap, int lda_p,
                 const float* __restrict__ Bp, int ldb,
                 float* __restrict__ Cp,
                 int M, int N, int K,
                 const float* __restrict__ bias1,
                 const float* __restrict__ bias2,
                 int t) {
    __shared__ __align__(16) float As[32][68];
    __shared__ __align__(16) float Bs[32][132];
    __shared__ int s_tok[64];

    const int tid = threadIdx.x;
    const int bm = blockIdx.y * 64;
    const int bn = blockIdx.x * 128;
    const int tm = tid >> 4;   // 0..15
    const int tn = tid & 15;   // 0..15

    const float* A;
    int lda;
    if (MODE == 3)      { A = Ap;    lda = lda_p; }
    else if (MODE == 0) { A = g_ctx; lda = HID;   }
    else                { A = g_h;   lda = HID;   }

    if (MODE == 1 && tid < 64) {
        int b = bm + tid;
        s_tok[tid] = (t == 0) ? 1 : decode_tok(g_tokpack[b]);
    }

    ull acc[4][4];
    #pragma unroll
    for (int i = 0; i < 4; i++)
        #pragma unroll
        for (int j = 0; j < 4; j++) acc[i][j] = 0ull;

    const int lr = tid >> 3;  // 0..31
    const int lq = tid & 7;   // 0..7

    for (int k0 = 0; k0 < K; k0 += 32) {
        #pragma unroll
        for (int p = 0; p < 2; p++) {
            int r = lr + p * 32;
            int row = bm + r;
            float4 v = make_float4(0.f, 0.f, 0.f, 0.f);
            if (row < M)
                v = *reinterpret_cast<const float4*>(A + (size_t)row * lda + k0 + lq * 4);
            As[lq * 4 + 0][r] = v.x;
            As[lq * 4 + 1][r] = v.y;
            As[lq * 4 + 2][r] = v.z;
            As[lq * 4 + 3][r] = v.w;
        }
        #pragma unroll
        for (int p = 0; p < 4; p++) {
            int r = lr + p * 32;
            int row = bn + r;
            float4 v = make_float4(0.f, 0.f, 0.f, 0.f);
            if (row < N)
                v = *reinterpret_cast<const float4*>(Bp + (size_t)row * ldb + k0 + lq * 4);
            Bs[lq * 4 + 0][r] = v.x;
            Bs[lq * 4 + 1][r] = v.y;
            Bs[lq * 4 + 2][r] = v.z;
            Bs[lq * 4 + 3][r] = v.w;
        }
        __syncthreads();

        #pragma unroll
        for (int kk = 0; kk < 32; kk++) {
            float4 av = *reinterpret_cast<const float4*>(&As[kk][tm * 4]);
            ulonglong2 b0 = *reinterpret_cast<const ulonglong2*>(&Bs[kk][tn * 8]);
            ulonglong2 b1 = *reinterpret_cast<const ulonglong2*>(&Bs[kk][tn * 8 + 4]);
            ull aa;
            aa = bcast2(av.x);
            acc[0][0] = ffma2(aa, b0.x, acc[0][0]);
            acc[0][1] = ffma2(aa, b0.y, acc[0][1]);
            acc[0][2] = ffma2(aa, b1.x, acc[0][2]);
            acc[0][3] = ffma2(aa, b1.y, acc[0][3]);
            aa = bcast2(av.y);
            acc[1][0] = ffma2(aa, b0.x, acc[1][0]);
            acc[1][1] = ffma2(aa, b0.y, acc[1][1]);
            acc[1][2] = ffma2(aa, b1.x, acc[1][2]);
            acc[1][3] = ffma2(aa, b1.y, acc[1][3]);
            aa = bcast2(av.z);
            acc[2][0] = ffma2(aa, b0.x, acc[2][0]);
            acc[2][1] = ffma2(aa, b0.y, acc[2][1]);
            acc[2][2] = ffma2(aa, b1.x, acc[2][2]);
            acc[2][3] = ffma2(aa, b1.y, acc[2][3]);
            aa = bcast2(av.w);
            acc[3][0] = ffma2(aa, b0.x, acc[3][0]);
            acc[3][1] = ffma2(aa, b0.y, acc[3][1]);
            acc[3][2] = ffma2(aa, b1.x, acc[3][2]);
            acc[3][3] = ffma2(aa, b1.y, acc[3][3]);
        }
        __syncthreads();
    }

    // epilogue
    float cv[4][8];
    #pragma unroll
    for (int i = 0; i < 4; i++)
        #pragma unroll
        for (int j = 0; j < 4; j++) {
            float2 p = unpack2(acc[i][j]);
            cv[i][2 * j]     = p.x;
            cv[i][2 * j + 1] = p.y;
        }

    if (MODE == 0 || MODE == 3) {
        #pragma unroll
        for (int i = 0; i < 4; i++) {
            int m = bm + tm * 4 + i;
            if (m >= M) continue;
            float* crow = (MODE == 0 ? g_Gbase : g_Eproj) + (size_t)m * N;
            #pragma unroll
            for (int j = 0; j < 8; j++) {
                int n = bn + tn * 8 + j;
                if (n >= N) continue;
                float v = cv[i][j];
                if (bias1) v += bias1[n];
                if (bias2) v += bias2[n];
                crow[n] = v;
            }
        }
    } else if (MODE == 1) {
        #pragma unroll
        for (int i = 0; i < 4; i++) {
            int m = bm + tm * 4 + i;
            int tok = s_tok[tm * 4 + i];
            const float* gb = g_Gbase + (size_t)m * NGATE;
            const float* ep = g_Eproj + (size_t)tok * NGATE;
            float* crow = g_gates + (size_t)m * NGATE;
            #pragma unroll
            for (int j = 0; j < 8; j++) {
                int n = bn + tn * 8 + j;
                crow[n] = cv[i][j] + gb[n] + ep[n];
            }
        }
    } else {  // MODE 2: logits + argmax
        #pragma unroll
        for (int i = 0; i < 4; i++) {
            int m = bm + tm * 4 + i;
            ull best = 0ull;
            #pragma unroll
            for (int j = 0; j < 8; j++) {
                int n = bn + tn * 8 + j;
                if (n < N) {
                    float v = cv[i][j] + bias1[n];
                    if (Cp)
                        Cp[(size_t)m * (TSTEPS * VOCAB) + (size_t)t * VOCAB + n] = v;
                    ull cand = ((ull)f2ord(v) << 32) | (ull)(0xFFFFFFFFu - (unsigned)n);
                    if (cand > best) best = cand;
                }
            }
            #pragma unroll
            for (int off = 8; off > 0; off >>= 1) {
                ull o = __shfl_xor_sync(0xffffffffu, best, off, 16);
                if (o > best) best = o;
            }
            if (tn == 0) atomicMax(&g_tokpack[m], best);
        }
    }
}

// ---------------- LSTM pointwise + pred write + tokpack reset ---------------
__global__ void lstm_pointwise_kernel(int t, float* __restrict__ pred) {
    int b = blockIdx.x, u = threadIdx.x;
    const float* g = g_gates + (size_t)b * NGATE;
    float gi = g[u];
    float gf = g[512 + u];
    float gg = g[1024 + u];
    float go = g[1536 + u];
    float c = g_c[b * HID + u];
    float cn = sigmoidf_(gf) * c + sigmoidf_(gi) * tanhf(gg);
    g_c[b * HID + u] = cn;
    g_h[b * HID + u] = sigmoidf_(go) * tanhf(cn);
    if (u == 0) {
        if (pred && t > 0)
            pred[b * TSTEPS + (t - 1)] = (float)decode_tok(g_tokpack[b]);
        g_tokpack[b] = 0ull;   // reset for this step's logits argmax
    }
}

__global__ void final_pred_kernel(float* __restrict__ pred) {
    int b = threadIdx.x;
    pred[b * TSTEPS + (TSTEPS - 1)] = (float)decode_tok(g_tokpack[b]);
}

// ---------------- launch ----------------
extern "C" void kernel_launch(void* const* d_in, const int* in_sizes, int n_in,
                              void* d_out, int out_size) {
    const float* enc_last = (const float*)d_in[0];   // [1,512,512]
    const float* enc_out  = (const float*)d_in[1];   // [512,80,512]
    const float* emb      = (const float*)d_in[2];   // [4004,1024]
    const float* w1       = (const float*)d_in[3];   // [512,1024]
    const float* w2       = (const float*)d_in[5];   // [512,512]
    const float* w3       = (const float*)d_in[7];   // [512,512]
    const float* wv       = (const float*)d_in[9];   // [1,512]
    const float* w_ih     = (const float*)d_in[10];  // [2048,1536]
    const float* w_hh     = (const float*)d_in[11];  // [2048,512]
    const float* b_ih     = (const float*)d_in[12];  // [2048]
    const float* b_hh     = (const float*)d_in[13];  // [2048]
    const float* out_w    = (const float*)d_in[14];  // [4004,512]
    const float* out_b    = (const float*)d_in[15];  // [4004]

    float* out = (float*)d_out;
    const long long SEQ  = (long long)BATCH * TSTEPS * VOCAB;   // 55,351,296
    const long long PRED = (long long)BATCH * TSTEPS;           // 13,824
    float* seq_ptr  = ((long long)out_size >= SEQ) ? out : nullptr;
    float* pred_ptr = ((long long)out_size >= SEQ + PRED) ? (out + SEQ) : nullptr;

    // --- precompute (attention is step-invariant; embedding path pre-projected)
    init_hc_kernel<<<BATCH, HID>>>(enc_last);
    matvecT_kernel<<<HID, 256>>>(w3, HID, wv, 0);       // a2 = W3^T wv
    matvecT_kernel<<<HID, 256>>>(w2, HID, nullptr, 1);  // a1 = W2^T a2
    matvecT_kernel<<<HID, 256>>>(w1, WDIM, nullptr, 2); // a0e = (W1^T a1)[:512]
    attn_ctx_kernel<<<BATCH, 256>>>(enc_out);

    // G_base = ctx @ W_ih[:,1024:]^T + b_ih + b_hh
    gemm_kernel<0><<<dim3(NGATE / 128, BATCH / 64), 256>>>(
        nullptr, 0, w_ih + WDIM, LSTM_IN, nullptr,
        BATCH, NGATE, HID, b_ih, b_hh, 0);

    // E_proj = embedding @ W_ih[:, :1024]^T
    gemm_kernel<3><<<dim3(NGATE / 128, (VOCAB + 63) / 64), 256>>>(
        emb, WDIM, w_ih, LSTM_IN, nullptr,
        VOCAB, NGATE, WDIM, nullptr, nullptr, 0);

    // --- 27 sequential decode steps
    for (int t = 0; t < TSTEPS; t++) {
        // gates = h @ W_hh^T + G_base + E_proj[tok]
        gemm_kernel<1><<<dim3(NGATE / 128, BATCH / 64), 256>>>(
            nullptr, 0, w_hh, HID, nullptr,
            BATCH, NGATE, HID, nullptr, nullptr, t);
        // LSTM cell update; also writes pred[t-1] and resets tokpack
        lstm_pointwise_kernel<<<BATCH, HID>>>(t, pred_ptr);
        // logits = h_new @ out_w^T + out_b ; fused argmax -> tokpack
        gemm_kernel<2><<<dim3((VOCAB + 127) / 128, BATCH / 64), 256>>>(
            nullptr, 0, out_w, HID, seq_ptr,
            BATCH, VOCAB, HID, out_b, nullptr, t);
    }
    if (pred_ptr)
        final_pred_kernel<<<1, BATCH>>>(pred_ptr);
}

// round 2
// speedup vs baseline: 1.2970x; 1.2970x over previous
#include <cuda_runtime.h>
#include <math.h>

// Problem constants
#define BATCH 512
#define HID   512
#define WDIM  1024
#define VOCAB 4004
#define TSTEPS 27
#define SLEN  80
#define NGATE 2048          // 4*HID
#define LSTM_IN 1536        // WDIM + HID

typedef unsigned long long ull;

// ---------------- scratch (device globals; allocation-free) ----------------
__device__ float g_a2[HID];
__device__ float g_a1[HID];
__device__ float g_a0e[HID];
__device__ float g_ctx[BATCH * HID];
__device__ float g_hbuf[2][BATCH * HID];
__device__ float g_c[BATCH * HID];
__device__ float g_Gbase[BATCH * NGATE];      // permuted cols: ctx @ W_ih_ctx^T + b_ih + b_hh
__device__ float g_Eproj[VOCAB * NGATE];      // permuted cols: embedding @ W_ih_word^T
__device__ ull   g_tokpack[2][BATCH];

// ---------------- small helpers ----------------
__device__ __forceinline__ ull ffma2(ull a, ull b, ull c) {
    ull d;
    asm("fma.rn.f32x2 %0, %1, %2, %3;" : "=l"(d) : "l"(a), "l"(b), "l"(c));
    return d;
}
__device__ __forceinline__ ull bcast2(float x) {
    ull r;
    asm("mov.b64 %0, {%1, %2};" : "=l"(r) : "f"(x), "f"(x));
    return r;
}
__device__ __forceinline__ float2 unpack2(ull v) {
    float2 r;
    asm("mov.b64 {%0, %1}, %2;" : "=f"(r.x), "=f"(r.y) : "l"(v));
    return r;
}
__device__ __forceinline__ unsigned f2ord(float x) {
    unsigned u = __float_as_uint(x);
    return (u & 0x80000000u) ? ~u : (u | 0x80000000u);
}
__device__ __forceinline__ int decode_tok(ull p) {
    return (int)(0xFFFFFFFFu - (unsigned)(p & 0xFFFFFFFFull));
}
__device__ __forceinline__ float sigmoidf_(float x) {
    return 1.0f / (1.0f + expf(-x));
}
// gate-interleaved permutation: col n = unit*4+gate  ->  original row gate*512+unit
__device__ __forceinline__ int permrow(int n) {
    return ((n & 3) << 9) | (n >> 2);
}

// ---------------- init h, c, tokpack ----------------
__global__ void init_hc_kernel(const float* __restrict__ h0) {
    int b = blockIdx.x, u = threadIdx.x;
    g_hbuf[0][b * HID + u] = h0[b * HID + u];
    g_c[b * HID + u] = 0.0f;
    if (u == 0) { g_tokpack[0][b] = 0ull; g_tokpack[1][b] = 0ull; }
}

// ---------------- a-chain mat-vecs: out[j] = sum_h M[h,j] * vin[h] ----------
__global__ void matvecT_kernel(const float* __restrict__ Mt, int ld,
                               const float* __restrict__ vin_ext, int stage) {
    __shared__ float red[256];
    int j = blockIdx.x;
    const float* vin = (stage == 0) ? vin_ext : (stage == 1 ? g_a2 : g_a1);
    float acc = 0.0f;
    for (int h = threadIdx.x; h < HID; h += 256)
        acc += Mt[(size_t)h * ld + j] * vin[h];
    red[threadIdx.x] = acc;
    __syncthreads();
    for (int s = 128; s > 0; s >>= 1) {
        if (threadIdx.x < s) red[threadIdx.x] += red[threadIdx.x + s];
        __syncthreads();
    }
    if (threadIdx.x == 0) {
        float r = red[0];
        if (stage == 0)      g_a2[j]  = r;
        else if (stage == 1) g_a1[j]  = r;
        else                 g_a0e[j] = r;
    }
}

// ---------------- attention softmax + context (step-invariant) --------------
__global__ void attn_ctx_kernel(const float* __restrict__ enc) {
    __shared__ float sa[HID];
    __shared__ float sE[SLEN];
    __shared__ float sW[SLEN];
    int b = blockIdx.x;
    int tid = threadIdx.x;

    sa[tid]       = g_a0e[tid];
    sa[tid + 256] = g_a0e[tid + 256];
    __syncthreads();

    int w = tid >> 5, lane = tid & 31;
    for (int s = w; s < SLEN; s += 8) {
        const float* row = enc + ((size_t)b * SLEN + s) * HID;
        float acc = 0.0f;
        for (int k = lane; k < HID; k += 32) acc += row[k] * sa[k];
        #pragma unroll
        for (int off = 16; off > 0; off >>= 1)
            acc += __shfl_xor_sync(0xffffffffu, acc, off);
        if (lane == 0) sE[s] = acc;
    }
    __syncthreads();

    if (tid < 32) {
        float v0 = (tid      < SLEN) ? sE[tid]      : -INFINITY;
        float v1 = (tid + 32 < SLEN) ? sE[tid + 32] : -INFINITY;
        float v2 = (tid + 64 < SLEN) ? sE[tid + 64] : -INFINITY;
        float m = fmaxf(v0, fmaxf(v1, v2));
        #pragma unroll
        for (int off = 16; off > 0; off >>= 1)
            m = fmaxf(m, __shfl_xor_sync(0xffffffffu, m, off));
        float e0 = (tid      < SLEN) ? expf(v0 - m) : 0.0f;
        float e1 = (tid + 32 < SLEN) ? expf(v1 - m) : 0.0f;
        float e2 = (tid + 64 < SLEN) ? expf(v2 - m) : 0.0f;
        float s = e0 + e1 + e2;
        #pragma unroll
        for (int off = 16; off > 0; off >>= 1)
            s += __shfl_xor_sync(0xffffffffu, s, off);
        if (tid      < SLEN) sW[tid]      = e0 / s;
        if (tid + 32 < SLEN) sW[tid + 32] = e1 / s;
        if (tid + 64 < SLEN) sW[tid + 64] = e2 / s;
    }
    __syncthreads();

    for (int h = tid; h < HID; h += 256) {
        float acc = 0.0f;
        for (int s = 0; s < SLEN; s++)
            acc += sW[s] * enc[((size_t)b * SLEN + s) * HID + h];
        g_ctx[b * HID + h] = acc;
    }
}

// ---------------- fp32x2 GEMM, BM=64 BN=64 BK=32, 256 thr, 4x4 tile --------
// MODE 0: Gbase  = ctx @ W_ih_ctx^T (B rows permuted; +b_ih+b_hh permuted)
// MODE 1: gates  = h @ W_hh^T (perm) + Gbase + Eproj[tok]; fused LSTM -> h,c
// MODE 2: logits = h @ out_w^T + out_b; store seq + fused argmax
// MODE 3: Eproj  = emb @ W_ih_word^T (B rows permuted)
template <int MODE>
__global__ __launch_bounds__(256, 3)
void gemm_kernel(const float* __restrict__ Ap,
                 const float* __restrict__ Bp, int ldb,
                 float* __restrict__ Cp,
                 int M, int N, int K,
                 const float* __restrict__ bias1,
                 const float* __restrict__ bias2,
                 int t, float* __restrict__ pred) {
    __shared__ __align__(16) float As[32][68];
    __shared__ __align__(16) float Bs[32][68];
    __shared__ int s_tok[64];

    const int tid = threadIdx.x;
    const int bm = blockIdx.y * 64;
    const int bn = blockIdx.x * 64;
    const int tm = tid >> 4;   // 0..15
    const int tn = tid & 15;   // 0..15

    const float* A;
    if (MODE == 3)      A = Ap;
    else if (MODE == 0) A = g_ctx;
    else                A = g_hbuf[(MODE == 1) ? (t & 1) : ((t + 1) & 1)];
    const int lda = (MODE == 3) ? WDIM : HID;

    if (MODE == 1 && tid < 64) {
        int b = bm + tid;
        s_tok[tid] = (t == 0) ? 1 : decode_tok(g_tokpack[(t - 1) & 1][b]);
    }
    if (MODE == 2 && blockIdx.x == 0 && tid < 64)
        g_tokpack[(t + 1) & 1][bm + tid] = 0ull;   // prep buffer for next step

    ull acc[4][2];
    #pragma unroll
    for (int i = 0; i < 4; i++) { acc[i][0] = 0ull; acc[i][1] = 0ull; }

    const int lr = tid >> 3;  // 0..31
    const int lq = tid & 7;   // 0..7

    for (int k0 = 0; k0 < K; k0 += 32) {
        #pragma unroll
        for (int p = 0; p < 2; p++) {
            int r = lr + p * 32;
            int row = bm + r;
            float4 v = make_float4(0.f, 0.f, 0.f, 0.f);
            if (MODE != 3 || row < M)
                v = *reinterpret_cast<const float4*>(A + (size_t)row * lda + k0 + lq * 4);
            As[lq * 4 + 0][r] = v.x;
            As[lq * 4 + 1][r] = v.y;
            As[lq * 4 + 2][r] = v.z;
            As[lq * 4 + 3][r] = v.w;
        }
        #pragma unroll
        for (int p = 0; p < 2; p++) {
            int r = lr + p * 32;
            int row = bn + r;
            float4 v = make_float4(0.f, 0.f, 0.f, 0.f);
            if (MODE == 2) {
                if (row < N)
                    v = *reinterpret_cast<const float4*>(Bp + (size_t)row * ldb + k0 + lq * 4);
            } else {
                int brow = permrow(row);
                v = *reinterpret_cast<const float4*>(Bp + (size_t)brow * ldb + k0 + lq * 4);
            }
            Bs[lq * 4 + 0][r] = v.x;
            Bs[lq * 4 + 1][r] = v.y;
            Bs[lq * 4 + 2][r] = v.z;
            Bs[lq * 4 + 3][r] = v.w;
        }
        __syncthreads();

        #pragma unroll
        for (int kk = 0; kk < 32; kk++) {
            float4 av = *reinterpret_cast<const float4*>(&As[kk][tm * 4]);
            ulonglong2 bv = *reinterpret_cast<const ulonglong2*>(&Bs[kk][tn * 4]);
            ull aa;
            aa = bcast2(av.x);
            acc[0][0] = ffma2(aa, bv.x, acc[0][0]);
            acc[0][1] = ffma2(aa, bv.y, acc[0][1]);
            aa = bcast2(av.y);
            acc[1][0] = ffma2(aa, bv.x, acc[1][0]);
            acc[1][1] = ffma2(aa, bv.y, acc[1][1]);
            aa = bcast2(av.z);
            acc[2][0] = ffma2(aa, bv.x, acc[2][0]);
            acc[2][1] = ffma2(aa, bv.y, acc[2][1]);
            aa = bcast2(av.w);
            acc[3][0] = ffma2(aa, bv.x, acc[3][0]);
            acc[3][1] = ffma2(aa, bv.y, acc[3][1]);
        }
        __syncthreads();
    }

    // unpack accumulators
    float cv[4][4];
    #pragma unroll
    for (int i = 0; i < 4; i++) {
        float2 p0 = unpack2(acc[i][0]);
        float2 p1 = unpack2(acc[i][1]);
        cv[i][0] = p0.x; cv[i][1] = p0.y; cv[i][2] = p1.x; cv[i][3] = p1.y;
    }
    const int ncol = bn + tn * 4;

    if (MODE == 0 || MODE == 3) {
        float badd[4] = {0.f, 0.f, 0.f, 0.f};
        if (MODE == 0) {
            #pragma unroll
            for (int j = 0; j < 4; j++) {
                int pr = permrow(ncol + j);
                badd[j] = bias1[pr] + bias2[pr];
            }
        }
        float* Cbase = (MODE == 0) ? g_Gbase : g_Eproj;
        #pragma unroll
        for (int i = 0; i < 4; i++) {
            int m = bm + tm * 4 + i;
            if (MODE == 3 && m >= M) continue;
            float4 v = make_float4(cv[i][0] + badd[0], cv[i][1] + badd[1],
                                   cv[i][2] + badd[2], cv[i][3] + badd[3]);
            *reinterpret_cast<float4*>(Cbase + (size_t)m * NGATE + ncol) = v;
        }
    } else if (MODE == 1) {
        // fused LSTM: this thread's 4 cols are the (i,f,g,o) of unit u
        const int u = ncol >> 2;
        float* hw = g_hbuf[(t + 1) & 1];
        #pragma unroll
        for (int i = 0; i < 4; i++) {
            int m = bm + tm * 4 + i;
            int tok = s_tok[tm * 4 + i];
            float4 gb = *reinterpret_cast<const float4*>(g_Gbase + (size_t)m * NGATE + ncol);
            float4 ep = *reinterpret_cast<const float4*>(g_Eproj + (size_t)tok * NGATE + ncol);
            float gi = cv[i][0] + gb.x + ep.x;
            float gf = cv[i][1] + gb.y + ep.y;
            float gg = cv[i][2] + gb.z + ep.z;
            float go = cv[i][3] + gb.w + ep.w;
            float c_old = g_c[m * HID + u];
            float cn = sigmoidf_(gf) * c_old + sigmoidf_(gi) * tanhf(gg);
            g_c[m * HID + u] = cn;
            hw[m * HID + u] = sigmoidf_(go) * tanhf(cn);
            if (blockIdx.x == 0 && tn == 0 && t > 0 && pred)
                pred[m * TSTEPS + (t - 1)] = (float)tok;
        }
    } else {  // MODE 2: logits + argmax
        #pragma unroll
        for (int i = 0; i < 4; i++) {
            int m = bm + tm * 4 + i;
            ull best = 0ull;
            #pragma unroll
            for (int j = 0; j < 4; j++) {
                int n = ncol + j;
                if (n < N) {
                    float v = cv[i][j] + bias1[n];
                    if (Cp)
                        Cp[(size_t)m * (TSTEPS * VOCAB) + (size_t)t * VOCAB + n] = v;
                    ull cand = ((ull)f2ord(v) << 32) | (ull)(0xFFFFFFFFu - (unsigned)n);
                    if (cand > best) best = cand;
                }
            }
            #pragma unroll
            for (int off = 8; off > 0; off >>= 1) {
                ull o = __shfl_xor_sync(0xffffffffu, best, off, 16);
                if (o > best) best = o;
            }
            if (tn == 0) atomicMax(&g_tokpack[t & 1][m], best);
        }
    }
}

// ---------------- final pred ----------------
__global__ void final_pred_kernel(float* __restrict__ pred) {
    int b = threadIdx.x;
    pred[b * TSTEPS + (TSTEPS - 1)] = (float)decode_tok(g_tokpack[(TSTEPS - 1) & 1][b]);
}

// ---------------- launch ----------------
extern "C" void kernel_launch(void* const* d_in, const int* in_sizes, int n_in,
                              void* d_out, int out_size) {
    const float* enc_last = (const float*)d_in[0];   // [1,512,512]
    const float* enc_out  = (const float*)d_in[1];   // [512,80,512]
    const float* emb      = (const float*)d_in[2];   // [4004,1024]
    const float* w1       = (const float*)d_in[3];   // [512,1024]
    const float* w2       = (const float*)d_in[5];   // [512,512]
    const float* w3       = (const float*)d_in[7];   // [512,512]
    const float* wv       = (const float*)d_in[9];   // [1,512]
    const float* w_ih     = (const float*)d_in[10];  // [2048,1536]
    const float* w_hh     = (const float*)d_in[11];  // [2048,512]
    const float* b_ih     = (const float*)d_in[12];  // [2048]
    const float* b_hh     = (const float*)d_in[13];  // [2048]
    const float* out_w    = (const float*)d_in[14];  // [4004,512]
    const float* out_b    = (const float*)d_in[15];  // [4004]

    float* out = (float*)d_out;
    const long long SEQ  = (long long)BATCH * TSTEPS * VOCAB;
    const long long PRED = (long long)BATCH * TSTEPS;
    float* seq_ptr  = ((long long)out_size >= SEQ) ? out : nullptr;
    float* pred_ptr = ((long long)out_size >= SEQ + PRED) ? (out + SEQ) : nullptr;

    // --- precompute
    init_hc_kernel<<<BATCH, HID>>>(enc_last);
    matvecT_kernel<<<HID, 256>>>(w3, HID, wv, 0);       // a2 = W3^T wv
    matvecT_kernel<<<HID, 256>>>(w2, HID, nullptr, 1);  // a1 = W2^T a2
    matvecT_kernel<<<HID, 256>>>(w1, WDIM, nullptr, 2); // a0e = (W1^T a1)[:512]
    attn_ctx_kernel<<<BATCH, 256>>>(enc_out);

    // G_base (permuted cols) = ctx @ W_ih_ctx^T + b_ih + b_hh
    gemm_kernel<0><<<dim3(NGATE / 64, BATCH / 64), 256>>>(
        nullptr, w_ih + WDIM, LSTM_IN, nullptr,
        BATCH, NGATE, HID, b_ih, b_hh, 0, nullptr);

    // E_proj (permuted cols) = embedding @ W_ih_word^T
    gemm_kernel<3><<<dim3(NGATE / 64, (VOCAB + 63) / 64), 256>>>(
        emb, w_ih, LSTM_IN, nullptr,
        VOCAB, NGATE, WDIM, nullptr, nullptr, 0, nullptr);

    // --- 27 sequential decode steps (2 launches each)
    for (int t = 0; t < TSTEPS; t++) {
        // gates + fused LSTM -> h_new, c ; also writes pred[t-1]
        gemm_kernel<1><<<dim3(NGATE / 64, BATCH / 64), 256>>>(
            nullptr, w_hh, HID, nullptr,
            BATCH, NGATE, HID, nullptr, nullptr, t, pred_ptr);
        // logits + bias + store + fused argmax
        gemm_kernel<2><<<dim3((VOCAB + 63) / 64, BATCH / 64), 256>>>(
            nullptr, out_w, HID, seq_ptr,
            BATCH, VOCAB, HID, out_b, nullptr, t, nullptr);
    }
    if (pred_ptr)
        final_pred_kernel<<<1, BATCH>>>(pred_ptr);
}